// round 10
// baseline (speedup 1.0000x reference)
#include <cuda_runtime.h>
#include <math.h>

#define Nn   64
#define Cc   3
#define Hh   384
#define Ww   384
#define Kk   3
#define HW   (Hh*Ww)        // 147456
#define NCHW (Nn*Cc*HW)     // 28311552
#define HW4  (HW/4)
#define CHW4 (Cc*HW4)

__device__ float g_lamsum[Nn];

// ---------------------------------------------------------------------------
__device__ __forceinline__ int reflect_idx(int q, int L) {
    return q < 0 ? -q : (q >= L ? 2 * L - 2 - q : q);
}

// ---------------------------------------------------------------------------
__global__ void k_init(const int* __restrict__ j_idx, float* __restrict__ out,
                       int write_flags) {
    int i = threadIdx.x;
    if (i < Nn) {
        g_lamsum[i] = 0.0f;
        if (write_flags)
            out[(long long)2 * NCHW + i] = (j_idx[i] == i) ? 1.0f : 0.0f;
    }
}

// ---------------------------------------------------------------------------
// k_mask: analytic mask + rotate + blur + merge over K, fused with x_mix write.
// grid (12,12,64), block 256; 32x32 output tile per block.
__global__ __launch_bounds__(256)
void k_mask(const float* __restrict__ x,
            const float* __restrict__ lam,   const float* __restrict__ angle,
            const float* __restrict__ sigma, const float* __restrict__ mux,
            const float* __restrict__ muy,   const int* __restrict__ method,
            const int* __restrict__ ksize,   const int* __restrict__ cx,
            const int* __restrict__ cy,      const int* __restrict__ valid,
            const int* __restrict__ j_idx,   float* __restrict__ out)
{
    const int n   = blockIdx.z;
    const int tx0 = blockIdx.x * 32;
    const int ty0 = blockIdx.y * 32;
    const int tid = threadIdx.x;

    __shared__ float A[38 * 40];   // rotated mask halo
    __shared__ float B[32 * 40];   // vertically blurred
    __shared__ float Mv[32 * 32];  // merged-mask staging for vector epilogue
    __shared__ float W7[7];        // normalized blur weights
    __shared__ float red[8];

    float acc[4] = {0.f, 0.f, 0.f, 0.f};
    float vsum = 0.0f;

    for (int k = 0; k < Kk; k++) {
        const int sidx = n * Kk + k;
        const float vk = (float)valid[sidx];
        vsum += vk;
        if (vk == 0.0f) continue;            // invalid stage: no work at all

        // ---- per-stage constants (block-uniform) ----
        const float lamv = lam[sidx];
        const int   mth  = method[sidx];
        float rad = angle[sidx] * (float)(M_PI / 180.0);
        float c = cosf(rad);
        float s = sinf(rad);
        float root = sqrtf(fmaxf(1.0f - lamv, 0.0f));
        float half_w = floorf(floorf((float)Ww * root) * 0.5f);
        float half_h = floorf(floorf((float)Hh * root) * 0.5f);
        float cxf = (float)cx[sidx], cyf = (float)cy[sidx];
        float rx1 = fmaxf(cxf - half_w, 0.0f);
        float rx2 = fminf(cxf + half_w, (float)Ww);
        float ry1 = fmaxf(cyf - half_h, 0.0f);
        float ry2 = fminf(cyf + half_h, (float)Hh);
        float muxv = mux[sidx];
        float muyv = muy[sidx];
        float sig = root * ((float)(Hh > Ww ? Hh : Ww) / 4.0f);
        float r2 = 0.6931471805599453f * (2.0f * sig * sig + 1e-12f);

        // affine source coords: ix = c*gx - s*gy + TX ; iy = s*gx + c*gy + TY
        float bxc = 1.0f / (float)Ww - 1.0f;
        float byc = 1.0f / (float)Hh - 1.0f;
        float TX = 0.5f * (float)Ww * (c * bxc - s * byc) + 0.5f * (float)(Ww - 1);
        float TY = 0.5f * (float)Hh * (s * bxc + c * byc) + 0.5f * (float)(Hh - 1);

        // ---- fast-path probe: constant mask over tile halo? ----
        float bx0 = (float)(tx0 >= 3 ? tx0 - 3 : 0);
        float bx1 = (float)(tx0 + 34 < Ww ? tx0 + 34 : Ww - 1);
        float by0 = (float)(ty0 >= 3 ? ty0 - 3 : 0);
        float by1 = (float)(ty0 + 34 < Hh ? ty0 + 34 : Hh - 1);
        float ixA = c * bx0 - s * by0 + TX, iyA = s * bx0 + c * by0 + TY;
        float ixB = c * bx1 - s * by0 + TX, iyB = s * bx1 + c * by0 + TY;
        float ixC = c * bx0 - s * by1 + TX, iyC = s * bx0 + c * by1 + TY;
        float ixD = c * bx1 - s * by1 + TX, iyD = s * bx1 + c * by1 + TY;
        float ixmin = fminf(fminf(ixA, ixB), fminf(ixC, ixD));
        float ixmax = fmaxf(fmaxf(ixA, ixB), fmaxf(ixC, ixD));
        float iymin = fminf(fminf(iyA, iyB), fminf(iyC, iyD));
        float iymax = fmaxf(fmaxf(iyA, iyB), fmaxf(iyC, iyD));

        bool interior = (ixmin >= 1e-3f) && (ixmax <= (float)(Ww - 1) - 1e-3f)
                     && (iymin >= 1e-3f) && (iymax <= (float)(Hh - 1) - 1e-3f);

        bool fast = false;
        float cval = 0.0f;
        if (interior) {
            float sxl = ixmin - 1.001f, sxh = ixmax + 1.001f;
            float syl = iymin - 1.001f, syh = iymax + 1.001f;
            if (mth == 0) {
                fast = true; cval = lamv;
            } else if (mth == 1) {
                if (sxh < rx1 || sxl >= rx2 || syh < ry1 || syl >= ry2) {
                    fast = true; cval = 1.0f;
                } else if (sxl >= rx1 && sxh < rx2 && syl >= ry1 && syh < ry2) {
                    fast = true; cval = 0.0f;
                }
            } else {
                float dxm = fmaxf(fmaxf(sxl - muxv, muxv - sxh), 0.0f);
                float dym = fmaxf(fmaxf(syl - muyv, muyv - syh), 0.0f);
                float mind2 = dxm * dxm + dym * dym;
                float dxM = fmaxf(muxv - sxl, sxh - muxv);
                float dyM = fmaxf(muyv - syl, syh - muyv);
                float maxd2 = dxM * dxM + dyM * dyM;
                float slack = 1e-3f * r2 + 1e-2f;
                if (maxd2 < r2 - slack)      { fast = true; cval = 1.0f; }
                else if (mind2 > r2 + slack) { fast = true; cval = 0.0f; }
            }
        }

        if (fast) {   // blur of a constant is the constant
            float sv = fminf(fmaxf(cval, 0.0f), 1.0f) * vk;
            #pragma unroll
            for (int q = 0; q < 4; q++) acc[q] += sv;
            continue;
        }

        // ---- blur weights: one thread computes, broadcast via smem ----
        if (tid == 0) {
            float sg = sigma[sidx];
            int   ks = ksize[sidx];
            float halfk = (float)((ks - 1) >> 1);
            float w[7], wsum = 0.0f;
            #pragma unroll
            for (int j = 0; j < 7; j++) {
                float t = (float)(j - 3);
                float r = t / sg;
                float wv = (fabsf(t) <= halfk) ? expf(-0.5f * r * r) : 0.0f;
                w[j] = wv; wsum += wv;
            }
            #pragma unroll
            for (int j = 0; j < 7; j++) W7[j] = w[j] / wsum;
        }

        // ---- phase A: rotated mask on 38x38 halo (separable per method) ----
        if (mth == 0) {
            for (int i = tid; i < 38 * 38; i += 256) {
                int iyt = i / 38;
                int ixt = i - iyt * 38;
                float gy = (float)reflect_idx(ty0 - 3 + iyt, Hh);
                float gx = (float)reflect_idx(tx0 - 3 + ixt, Ww);
                float ix = c * gx - s * gy + TX;
                float iy = s * gx + c * gy + TY;
                float ix0 = floorf(ix), iy0 = floorf(iy);
                float wx = ix - ix0,    wy = iy - iy0;
                float owx = 1.0f - wx,  owy = 1.0f - wy;
                float vx0 = (ix0 >= 0.0f && ix0 < (float)Ww) ? 1.0f : 0.0f;
                float vx1 = (ix0 >= -1.0f && ix0 < (float)(Ww - 1)) ? 1.0f : 0.0f;
                float vy0 = (iy0 >= 0.0f && iy0 < (float)Hh) ? 1.0f : 0.0f;
                float vy1 = (iy0 >= -1.0f && iy0 < (float)(Hh - 1)) ? 1.0f : 0.0f;
                float Vx = owx * vx0 + wx * vx1;
                float Vy = owy * vy0 + wy * vy1;
                A[iyt * 40 + ixt] = lamv * Vx * Vy;
            }
        } else if (mth == 1) {
            for (int i = tid; i < 38 * 38; i += 256) {
                int iyt = i / 38;
                int ixt = i - iyt * 38;
                float gy = (float)reflect_idx(ty0 - 3 + iyt, Hh);
                float gx = (float)reflect_idx(tx0 - 3 + ixt, Ww);
                float ix = c * gx - s * gy + TX;
                float iy = s * gx + c * gy + TY;
                float ix0 = floorf(ix), iy0 = floorf(iy);
                float ix1 = ix0 + 1.0f,  iy1 = iy0 + 1.0f;
                float wx = ix - ix0,     wy = iy - iy0;
                float owx = 1.0f - wx,   owy = 1.0f - wy;
                float vx0 = (ix0 >= 0.0f && ix0 < (float)Ww) ? 1.0f : 0.0f;
                float vx1 = (ix1 >= 0.0f && ix1 < (float)Ww) ? 1.0f : 0.0f;
                float vy0 = (iy0 >= 0.0f && iy0 < (float)Hh) ? 1.0f : 0.0f;
                float vy1 = (iy1 >= 0.0f && iy1 < (float)Hh) ? 1.0f : 0.0f;
                float px0 = (ix0 >= rx1 && ix0 < rx2) ? vx0 : 0.0f;
                float px1 = (ix1 >= rx1 && ix1 < rx2) ? vx1 : 0.0f;
                float py0 = (iy0 >= ry1 && iy0 < ry2) ? vy0 : 0.0f;
                float py1 = (iy1 >= ry1 && iy1 < ry2) ? vy1 : 0.0f;
                float Vx = owx * vx0 + wx * vx1;
                float Vy = owy * vy0 + wy * vy1;
                float Px = owx * px0 + wx * px1;
                float Py = owy * py0 + wy * py1;
                A[iyt * 40 + ixt] = Vx * Vy - Px * Py;
            }
        } else {
            for (int i = tid; i < 38 * 38; i += 256) {
                int iyt = i / 38;
                int ixt = i - iyt * 38;
                float gy = (float)reflect_idx(ty0 - 3 + iyt, Hh);
                float gx = (float)reflect_idx(tx0 - 3 + ixt, Ww);
                float ix = c * gx - s * gy + TX;
                float iy = s * gx + c * gy + TY;
                float ix0 = floorf(ix), iy0 = floorf(iy);
                float ix1 = ix0 + 1.0f,  iy1 = iy0 + 1.0f;
                float wx = ix - ix0,     wy = iy - iy0;
                float owx = 1.0f - wx,   owy = 1.0f - wy;
                float vx0 = (ix0 >= 0.0f && ix0 < (float)Ww) ? 1.0f : 0.0f;
                float vx1 = (ix1 >= 0.0f && ix1 < (float)Ww) ? 1.0f : 0.0f;
                float vy0 = (iy0 >= 0.0f && iy0 < (float)Hh) ? 1.0f : 0.0f;
                float vy1 = (iy1 >= 0.0f && iy1 < (float)Hh) ? 1.0f : 0.0f;
                float dx0 = ix0 - muxv, dx1 = ix1 - muxv;
                float dy0 = iy0 - muyv, dy1 = iy1 - muyv;
                float dx0s = dx0 * dx0, dx1s = dx1 * dx1;
                float dy0s = dy0 * dy0, dy1s = dy1 * dy1;
                float i00 = (dx0s + dy0s < r2) ? vx0 * vy0 : 0.0f;
                float i10 = (dx1s + dy0s < r2) ? vx1 * vy0 : 0.0f;
                float i01 = (dx0s + dy1s < r2) ? vx0 * vy1 : 0.0f;
                float i11 = (dx1s + dy1s < r2) ? vx1 * vy1 : 0.0f;
                float row0 = owx * i00 + wx * i10;
                float row1 = owx * i01 + wx * i11;
                A[iyt * 40 + ixt] = owy * row0 + wy * row1;
            }
        }
        __syncthreads();   // A + W7 ready

        // ---- phase B: vertical 7-tap ----
        for (int i = tid; i < 32 * 38; i += 256) {
            int yy = i / 38;
            int ixt = i - yy * 38;
            float sv = 0.0f;
            #pragma unroll
            for (int j = 0; j < 7; j++) sv += W7[j] * A[(yy + j) * 40 + ixt];
            B[yy * 40 + ixt] = sv;
        }
        __syncthreads();

        // ---- phase C: horizontal 7-tap + clip + accumulate ----
        #pragma unroll
        for (int q = 0; q < 4; q++) {
            int p  = tid + q * 256;
            int yy = p >> 5;
            int xx = p & 31;
            float sv = 0.0f;
            #pragma unroll
            for (int j = 0; j < 7; j++) sv += W7[j] * B[yy * 40 + xx + j];
            acc[q] += fminf(fmaxf(sv, 0.0f), 1.0f) * vk;
        }
        __syncthreads();   // protect A/B/W7 for next stage
    }

    // ---- stage merged values into smem + lam_m partial ----
    float inv_v = 1.0f / vsum;
    int j = j_idx[n];
    float local = 0.0f;
    #pragma unroll
    for (int q = 0; q < 4; q++) {
        int p = tid + q * 256;           // p = yy*32 + xx
        float mv = acc[q] * inv_v;
        Mv[p] = mv;
        local += mv;
    }
    __syncthreads();

    // ---- vectorized x_mix epilogue: each thread owns 4 consecutive pixels ----
    {
        int yy = tid >> 3;
        int qx = (tid & 7) * 4;
        float4 m4 = *(const float4*)&Mv[yy * 32 + qx];
        int pix = (ty0 + yy) * Ww + tx0 + qx;
        #pragma unroll
        for (int ch = 0; ch < Cc; ch++) {
            int src = (n * Cc + ch) * HW + pix;
            int tgt = (j * Cc + ch) * HW + pix;
            float4 xv = __ldcs((const float4*)(x + src));   // read-once: evict first
            float4 xt = *(const float4*)(x + tgt);          // gathered: keep in L2
            float4 xo;
            xo.x = m4.x * xv.x + (1.0f - m4.x) * xt.x;
            xo.y = m4.y * xv.y + (1.0f - m4.y) * xt.y;
            xo.z = m4.z * xv.z + (1.0f - m4.z) * xt.z;
            xo.w = m4.w * xv.w + (1.0f - m4.w) * xt.w;
            __stcs((float4*)(out + src), xo);               // streaming store
        }
    }

    #pragma unroll
    for (int off = 16; off; off >>= 1)
        local += __shfl_down_sync(0xffffffffu, local, off);
    if ((tid & 31) == 0) red[tid >> 5] = local;
    __syncthreads();
    if (tid < 8) {
        float v = red[tid];
        #pragma unroll
        for (int off = 4; off; off >>= 1)
            v += __shfl_down_sync(0xffu, v, off);
        if (tid == 0) atomicAdd(&g_lamsum[n], v);
    }
}

// ---------------------------------------------------------------------------
// k_y: streaming float4 y_mix (needs complete lam_m)
__global__ __launch_bounds__(256)
void k_y(const float* __restrict__ y, const int* __restrict__ j_idx,
         float* __restrict__ out)
{
    const int total4 = NCHW / 4;
    int e = blockIdx.x * blockDim.x + threadIdx.x;
    if (e >= total4) return;

    int n   = e / CHW4;
    int rem = e - n * CHW4;
    int j = j_idx[n];
    float lm = g_lamsum[n] * (1.0f / (float)HW);

    const float4* y4 = (const float4*)y;
    float4 yv = __ldcs(&y4[e]);            // read-once: evict first
    float4 yt = y4[j * CHW4 + rem];        // gathered: keep in L2

    float4 yo;
    yo.x = lm * yv.x + (1.0f - lm) * yt.x;
    yo.y = lm * yv.y + (1.0f - lm) * yt.y;
    yo.z = lm * yv.z + (1.0f - lm) * yt.z;
    yo.w = lm * yv.w + (1.0f - lm) * yt.w;

    __stcs(((float4*)out) + total4 + e, yo);
}

// ---------------------------------------------------------------------------
extern "C" void kernel_launch(void* const* d_in, const int* in_sizes, int n_in,
                              void* d_out, int out_size)
{
    const float* x      = (const float*)d_in[0];
    const float* y      = (const float*)d_in[1];
    const float* lam    = (const float*)d_in[2];
    const float* angle  = (const float*)d_in[3];
    const float* sigma  = (const float*)d_in[4];
    const float* mux    = (const float*)d_in[5];
    const float* muy    = (const float*)d_in[6];
    const int*   j_idx  = (const int*)d_in[7];
    const int*   method = (const int*)d_in[8];
    const int*   ksize  = (const int*)d_in[9];
    const int*   cx     = (const int*)d_in[10];
    const int*   cy     = (const int*)d_in[11];
    const int*   valid  = (const int*)d_in[12];
    float* out = (float*)d_out;

    int write_flags = (out_size >= 2 * NCHW + Nn) ? 1 : 0;

    k_init<<<1, 64>>>(j_idx, out, write_flags);
    k_mask<<<dim3(12, 12, Nn), 256>>>(x, lam, angle, sigma, mux, muy,
                                      method, ksize, cx, cy, valid, j_idx, out);
    k_y<<<(NCHW / 4 + 255) / 256, 256>>>(y, j_idx, out);
}

// round 11
// speedup vs baseline: 1.0915x; 1.0915x over previous
#include <cuda_runtime.h>
#include <math.h>

#define Nn   64
#define Cc   3
#define Hh   384
#define Ww   384
#define Kk   3
#define HW   (Hh*Ww)        // 147456
#define NCHW (Nn*Cc*HW)     // 28311552
#define HW4  (HW/4)
#define CHW4 (Cc*HW4)

__device__ float g_lamsum[Nn];

// ---------------------------------------------------------------------------
__device__ __forceinline__ int reflect_idx(int q, int L) {
    return q < 0 ? -q : (q >= L ? 2 * L - 2 - q : q);
}

// ---------------------------------------------------------------------------
__global__ void k_init(const int* __restrict__ j_idx, float* __restrict__ out,
                       int write_flags) {
    int i = threadIdx.x;
    if (i < Nn) {
        g_lamsum[i] = 0.0f;
        if (write_flags)
            out[(long long)2 * NCHW + i] = (j_idx[i] == i) ? 1.0f : 0.0f;
    }
}

// ---------------------------------------------------------------------------
// k_mask: analytic mask + rotate + blur + merge over K, fused with x_mix write.
// grid (12,12,64), block 256; 32x32 output tile per block.
__global__ __launch_bounds__(256)
void k_mask(const float* __restrict__ x,
            const float* __restrict__ lam,   const float* __restrict__ angle,
            const float* __restrict__ sigma, const float* __restrict__ mux,
            const float* __restrict__ muy,   const int* __restrict__ method,
            const int* __restrict__ ksize,   const int* __restrict__ cx,
            const int* __restrict__ cy,      const int* __restrict__ valid,
            const int* __restrict__ j_idx,   float* __restrict__ out)
{
    const int n   = blockIdx.z;
    const int tx0 = blockIdx.x * 32;
    const int ty0 = blockIdx.y * 32;
    const int tid = threadIdx.x;

    __shared__ float A[38 * 40];   // rotated mask halo
    __shared__ float B[32 * 40];   // vertically blurred
    __shared__ float Mv[32 * 32];  // merged-mask staging for vector epilogue
    __shared__ float W7[7];        // normalized blur weights
    __shared__ float red[8];

    float acc[4] = {0.f, 0.f, 0.f, 0.f};
    float vsum = 0.0f;

    for (int k = 0; k < Kk; k++) {
        const int sidx = n * Kk + k;
        const float vk = (float)valid[sidx];
        vsum += vk;
        if (vk == 0.0f) continue;            // invalid stage: no work at all

        // ---- per-stage constants (block-uniform) ----
        const float lamv = lam[sidx];
        const int   mth  = method[sidx];
        float rad = angle[sidx] * (float)(M_PI / 180.0);
        float c = cosf(rad);
        float s = sinf(rad);
        float root = sqrtf(fmaxf(1.0f - lamv, 0.0f));
        float half_w = floorf(floorf((float)Ww * root) * 0.5f);
        float half_h = floorf(floorf((float)Hh * root) * 0.5f);
        float cxf = (float)cx[sidx], cyf = (float)cy[sidx];
        float rx1 = fmaxf(cxf - half_w, 0.0f);
        float rx2 = fminf(cxf + half_w, (float)Ww);
        float ry1 = fmaxf(cyf - half_h, 0.0f);
        float ry2 = fminf(cyf + half_h, (float)Hh);
        float muxv = mux[sidx];
        float muyv = muy[sidx];
        float sig = root * ((float)(Hh > Ww ? Hh : Ww) / 4.0f);
        float r2 = 0.6931471805599453f * (2.0f * sig * sig + 1e-12f);

        // affine source coords: ix = c*gx - s*gy + TX ; iy = s*gx + c*gy + TY
        float bxc = 1.0f / (float)Ww - 1.0f;
        float byc = 1.0f / (float)Hh - 1.0f;
        float TX = 0.5f * (float)Ww * (c * bxc - s * byc) + 0.5f * (float)(Ww - 1);
        float TY = 0.5f * (float)Hh * (s * bxc + c * byc) + 0.5f * (float)(Hh - 1);

        // ---- fast-path probe: constant mask over tile halo? ----
        float bx0 = (float)(tx0 >= 3 ? tx0 - 3 : 0);
        float bx1 = (float)(tx0 + 34 < Ww ? tx0 + 34 : Ww - 1);
        float by0 = (float)(ty0 >= 3 ? ty0 - 3 : 0);
        float by1 = (float)(ty0 + 34 < Hh ? ty0 + 34 : Hh - 1);
        float ixA = c * bx0 - s * by0 + TX, iyA = s * bx0 + c * by0 + TY;
        float ixB = c * bx1 - s * by0 + TX, iyB = s * bx1 + c * by0 + TY;
        float ixC = c * bx0 - s * by1 + TX, iyC = s * bx0 + c * by1 + TY;
        float ixD = c * bx1 - s * by1 + TX, iyD = s * bx1 + c * by1 + TY;
        float ixmin = fminf(fminf(ixA, ixB), fminf(ixC, ixD));
        float ixmax = fmaxf(fmaxf(ixA, ixB), fmaxf(ixC, ixD));
        float iymin = fminf(fminf(iyA, iyB), fminf(iyC, iyD));
        float iymax = fmaxf(fmaxf(iyA, iyB), fmaxf(iyC, iyD));

        bool interior = (ixmin >= 1e-3f) && (ixmax <= (float)(Ww - 1) - 1e-3f)
                     && (iymin >= 1e-3f) && (iymax <= (float)(Hh - 1) - 1e-3f);

        bool fast = false;
        float cval = 0.0f;
        if (interior) {
            float sxl = ixmin - 1.001f, sxh = ixmax + 1.001f;
            float syl = iymin - 1.001f, syh = iymax + 1.001f;
            if (mth == 0) {
                fast = true; cval = lamv;
            } else if (mth == 1) {
                if (sxh < rx1 || sxl >= rx2 || syh < ry1 || syl >= ry2) {
                    fast = true; cval = 1.0f;
                } else if (sxl >= rx1 && sxh < rx2 && syl >= ry1 && syh < ry2) {
                    fast = true; cval = 0.0f;
                }
            } else {
                float dxm = fmaxf(fmaxf(sxl - muxv, muxv - sxh), 0.0f);
                float dym = fmaxf(fmaxf(syl - muyv, muyv - syh), 0.0f);
                float mind2 = dxm * dxm + dym * dym;
                float dxM = fmaxf(muxv - sxl, sxh - muxv);
                float dyM = fmaxf(muyv - syl, syh - muyv);
                float maxd2 = dxM * dxM + dyM * dyM;
                float slack = 1e-3f * r2 + 1e-2f;
                if (maxd2 < r2 - slack)      { fast = true; cval = 1.0f; }
                else if (mind2 > r2 + slack) { fast = true; cval = 0.0f; }
            }
        }

        if (fast) {   // blur of a constant is the constant
            float sv = fminf(fmaxf(cval, 0.0f), 1.0f) * vk;
            #pragma unroll
            for (int q = 0; q < 4; q++) acc[q] += sv;
            continue;
        }

        // ---- blur weights: one thread computes, broadcast via smem ----
        if (tid == 0) {
            float sg = sigma[sidx];
            int   ks = ksize[sidx];
            float halfk = (float)((ks - 1) >> 1);
            float w[7], wsum = 0.0f;
            #pragma unroll
            for (int j = 0; j < 7; j++) {
                float t = (float)(j - 3);
                float r = t / sg;
                float wv = (fabsf(t) <= halfk) ? expf(-0.5f * r * r) : 0.0f;
                w[j] = wv; wsum += wv;
            }
            #pragma unroll
            for (int j = 0; j < 7; j++) W7[j] = w[j] / wsum;
        }

        // ---- phase A: rotated mask on 38x38 halo (separable per method) ----
        if (mth == 0) {
            for (int i = tid; i < 38 * 38; i += 256) {
                int iyt = i / 38;
                int ixt = i - iyt * 38;
                float gy = (float)reflect_idx(ty0 - 3 + iyt, Hh);
                float gx = (float)reflect_idx(tx0 - 3 + ixt, Ww);
                float ix = c * gx - s * gy + TX;
                float iy = s * gx + c * gy + TY;
                float ix0 = floorf(ix), iy0 = floorf(iy);
                float wx = ix - ix0,    wy = iy - iy0;
                float owx = 1.0f - wx,  owy = 1.0f - wy;
                float vx0 = (ix0 >= 0.0f && ix0 < (float)Ww) ? 1.0f : 0.0f;
                float vx1 = (ix0 >= -1.0f && ix0 < (float)(Ww - 1)) ? 1.0f : 0.0f;
                float vy0 = (iy0 >= 0.0f && iy0 < (float)Hh) ? 1.0f : 0.0f;
                float vy1 = (iy0 >= -1.0f && iy0 < (float)(Hh - 1)) ? 1.0f : 0.0f;
                float Vx = owx * vx0 + wx * vx1;
                float Vy = owy * vy0 + wy * vy1;
                A[iyt * 40 + ixt] = lamv * Vx * Vy;
            }
        } else if (mth == 1) {
            for (int i = tid; i < 38 * 38; i += 256) {
                int iyt = i / 38;
                int ixt = i - iyt * 38;
                float gy = (float)reflect_idx(ty0 - 3 + iyt, Hh);
                float gx = (float)reflect_idx(tx0 - 3 + ixt, Ww);
                float ix = c * gx - s * gy + TX;
                float iy = s * gx + c * gy + TY;
                float ix0 = floorf(ix), iy0 = floorf(iy);
                float ix1 = ix0 + 1.0f,  iy1 = iy0 + 1.0f;
                float wx = ix - ix0,     wy = iy - iy0;
                float owx = 1.0f - wx,   owy = 1.0f - wy;
                float vx0 = (ix0 >= 0.0f && ix0 < (float)Ww) ? 1.0f : 0.0f;
                float vx1 = (ix1 >= 0.0f && ix1 < (float)Ww) ? 1.0f : 0.0f;
                float vy0 = (iy0 >= 0.0f && iy0 < (float)Hh) ? 1.0f : 0.0f;
                float vy1 = (iy1 >= 0.0f && iy1 < (float)Hh) ? 1.0f : 0.0f;
                float px0 = (ix0 >= rx1 && ix0 < rx2) ? vx0 : 0.0f;
                float px1 = (ix1 >= rx1 && ix1 < rx2) ? vx1 : 0.0f;
                float py0 = (iy0 >= ry1 && iy0 < ry2) ? vy0 : 0.0f;
                float py1 = (iy1 >= ry1 && iy1 < ry2) ? vy1 : 0.0f;
                float Vx = owx * vx0 + wx * vx1;
                float Vy = owy * vy0 + wy * vy1;
                float Px = owx * px0 + wx * px1;
                float Py = owy * py0 + wy * py1;
                A[iyt * 40 + ixt] = Vx * Vy - Px * Py;
            }
        } else {
            for (int i = tid; i < 38 * 38; i += 256) {
                int iyt = i / 38;
                int ixt = i - iyt * 38;
                float gy = (float)reflect_idx(ty0 - 3 + iyt, Hh);
                float gx = (float)reflect_idx(tx0 - 3 + ixt, Ww);
                float ix = c * gx - s * gy + TX;
                float iy = s * gx + c * gy + TY;
                float ix0 = floorf(ix), iy0 = floorf(iy);
                float ix1 = ix0 + 1.0f,  iy1 = iy0 + 1.0f;
                float wx = ix - ix0,     wy = iy - iy0;
                float owx = 1.0f - wx,   owy = 1.0f - wy;
                float vx0 = (ix0 >= 0.0f && ix0 < (float)Ww) ? 1.0f : 0.0f;
                float vx1 = (ix1 >= 0.0f && ix1 < (float)Ww) ? 1.0f : 0.0f;
                float vy0 = (iy0 >= 0.0f && iy0 < (float)Hh) ? 1.0f : 0.0f;
                float vy1 = (iy1 >= 0.0f && iy1 < (float)Hh) ? 1.0f : 0.0f;
                float dx0 = ix0 - muxv, dx1 = ix1 - muxv;
                float dy0 = iy0 - muyv, dy1 = iy1 - muyv;
                float dx0s = dx0 * dx0, dx1s = dx1 * dx1;
                float dy0s = dy0 * dy0, dy1s = dy1 * dy1;
                float i00 = (dx0s + dy0s < r2) ? vx0 * vy0 : 0.0f;
                float i10 = (dx1s + dy0s < r2) ? vx1 * vy0 : 0.0f;
                float i01 = (dx0s + dy1s < r2) ? vx0 * vy1 : 0.0f;
                float i11 = (dx1s + dy1s < r2) ? vx1 * vy1 : 0.0f;
                float row0 = owx * i00 + wx * i10;
                float row1 = owx * i01 + wx * i11;
                A[iyt * 40 + ixt] = owy * row0 + wy * row1;
            }
        }
        __syncthreads();   // A + W7 ready

        // ---- phase B: vertical 7-tap ----
        for (int i = tid; i < 32 * 38; i += 256) {
            int yy = i / 38;
            int ixt = i - yy * 38;
            float sv = 0.0f;
            #pragma unroll
            for (int j = 0; j < 7; j++) sv += W7[j] * A[(yy + j) * 40 + ixt];
            B[yy * 40 + ixt] = sv;
        }
        __syncthreads();

        // ---- phase C: horizontal 7-tap + clip + accumulate ----
        #pragma unroll
        for (int q = 0; q < 4; q++) {
            int p  = tid + q * 256;
            int yy = p >> 5;
            int xx = p & 31;
            float sv = 0.0f;
            #pragma unroll
            for (int j = 0; j < 7; j++) sv += W7[j] * B[yy * 40 + xx + j];
            acc[q] += fminf(fmaxf(sv, 0.0f), 1.0f) * vk;
        }
        __syncthreads();   // protect A/B/W7 for next stage
    }

    // ---- stage merged values into smem + lam_m partial ----
    float inv_v = 1.0f / vsum;
    int j = j_idx[n];
    float local = 0.0f;
    #pragma unroll
    for (int q = 0; q < 4; q++) {
        int p = tid + q * 256;           // p = yy*32 + xx
        float mv = acc[q] * inv_v;
        Mv[p] = mv;
        local += mv;
    }
    __syncthreads();

    // ---- vectorized x_mix epilogue: each thread owns 4 consecutive pixels ----
    {
        int yy = tid >> 3;
        int qx = (tid & 7) * 4;
        float4 m4 = *(const float4*)&Mv[yy * 32 + qx];
        int pix = (ty0 + yy) * Ww + tx0 + qx;
        #pragma unroll
        for (int ch = 0; ch < Cc; ch++) {
            int src = (n * Cc + ch) * HW + pix;
            int tgt = (j * Cc + ch) * HW + pix;
            float4 xv = *(const float4*)(x + src);   // default caching: keep L2 reuse
            float4 xt = *(const float4*)(x + tgt);
            float4 xo;
            xo.x = m4.x * xv.x + (1.0f - m4.x) * xt.x;
            xo.y = m4.y * xv.y + (1.0f - m4.y) * xt.y;
            xo.z = m4.z * xv.z + (1.0f - m4.z) * xt.z;
            xo.w = m4.w * xv.w + (1.0f - m4.w) * xt.w;
            __stcs((float4*)(out + src), xo);        // out never re-read: evict first
        }
    }

    #pragma unroll
    for (int off = 16; off; off >>= 1)
        local += __shfl_down_sync(0xffffffffu, local, off);
    if ((tid & 31) == 0) red[tid >> 5] = local;
    __syncthreads();
    if (tid < 8) {
        float v = red[tid];
        #pragma unroll
        for (int off = 4; off; off >>= 1)
            v += __shfl_down_sync(0xffu, v, off);
        if (tid == 0) atomicAdd(&g_lamsum[n], v);
    }
}

// ---------------------------------------------------------------------------
// k_y: streaming float4 y_mix (needs complete lam_m)
__global__ __launch_bounds__(256)
void k_y(const float* __restrict__ y, const int* __restrict__ j_idx,
         float* __restrict__ out)
{
    const int total4 = NCHW / 4;
    int e = blockIdx.x * blockDim.x + threadIdx.x;
    if (e >= total4) return;

    int n   = e / CHW4;
    int rem = e - n * CHW4;
    int j = j_idx[n];
    float lm = g_lamsum[n] * (1.0f / (float)HW);

    const float4* y4 = (const float4*)y;
    float4 yv = y4[e];                     // default caching: keep L2 reuse
    float4 yt = y4[j * CHW4 + rem];

    float4 yo;
    yo.x = lm * yv.x + (1.0f - lm) * yt.x;
    yo.y = lm * yv.y + (1.0f - lm) * yt.y;
    yo.z = lm * yv.z + (1.0f - lm) * yt.z;
    yo.w = lm * yv.w + (1.0f - lm) * yt.w;

    __stcs(((float4*)out) + total4 + e, yo);
}

// ---------------------------------------------------------------------------
extern "C" void kernel_launch(void* const* d_in, const int* in_sizes, int n_in,
                              void* d_out, int out_size)
{
    const float* x      = (const float*)d_in[0];
    const float* y      = (const float*)d_in[1];
    const float* lam    = (const float*)d_in[2];
    const float* angle  = (const float*)d_in[3];
    const float* sigma  = (const float*)d_in[4];
    const float* mux    = (const float*)d_in[5];
    const float* muy    = (const float*)d_in[6];
    const int*   j_idx  = (const int*)d_in[7];
    const int*   method = (const int*)d_in[8];
    const int*   ksize  = (const int*)d_in[9];
    const int*   cx     = (const int*)d_in[10];
    const int*   cy     = (const int*)d_in[11];
    const int*   valid  = (const int*)d_in[12];
    float* out = (float*)d_out;

    int write_flags = (out_size >= 2 * NCHW + Nn) ? 1 : 0;

    k_init<<<1, 64>>>(j_idx, out, write_flags);
    k_mask<<<dim3(12, 12, Nn), 256>>>(x, lam, angle, sigma, mux, muy,
                                      method, ksize, cx, cy, valid, j_idx, out);
    k_y<<<(NCHW / 4 + 255) / 256, 256>>>(y, j_idx, out);
}